// round 5
// baseline (speedup 1.0000x reference)
#include <cuda_runtime.h>
#include <cuda_bf16.h>
#include <cstdint>

#define CIN 256
#define COUT 256
#define HH 56
#define WW 56
#define NN 8
#define KKER 9
#define HWSZ (HH*WW)            // 3136
#define M_TOTAL (NN*HWSZ)       // 25088
#define KD (KKER*CIN)           // 2304

// Scratch (device globals — no runtime allocation allowed)
__device__ float g_xnhwc[(size_t)NN*HWSZ*CIN];                  // 25.7 MB
__device__ __nv_bfloat16 g_Bhi[(size_t)COUT*KD];                // 1.18 MB
__device__ __nv_bfloat16 g_Blo[(size_t)COUT*KD];                // 1.18 MB

// ---------------------------------------------------------------------------
// helpers
// ---------------------------------------------------------------------------
__device__ __forceinline__ uint32_t smem_u32(const void* p) {
    uint32_t a;
    asm("{ .reg .u64 t; cvta.to.shared.u64 t, %1; cvt.u32.u64 %0, t; }"
        : "=r"(a) : "l"(p));
    return a;
}
__device__ __forceinline__ void cp_async16(uint32_t saddr, const void* gptr) {
    asm volatile("cp.async.cg.shared.global [%0], [%1], 16;"
                 :: "r"(saddr), "l"(__cvta_generic_to_global(gptr)) : "memory");
}
__device__ __forceinline__ void cp_commit() {
    asm volatile("cp.async.commit_group;" ::: "memory");
}
template <int N>
__device__ __forceinline__ void cp_wait() {
    asm volatile("cp.async.wait_group %0;" :: "n"(N) : "memory");
}
__device__ __forceinline__ void ldsm4(uint32_t* d, uint32_t addr) {
    asm volatile("ldmatrix.sync.aligned.m8n8.x4.shared.b16 {%0,%1,%2,%3}, [%4];"
                 : "=r"(d[0]), "=r"(d[1]), "=r"(d[2]), "=r"(d[3]) : "r"(addr));
}
__device__ __forceinline__ void mma_bf16(float* c, const uint32_t* a, const uint32_t* b) {
    asm volatile(
        "mma.sync.aligned.m16n8k16.row.col.f32.bf16.bf16.f32 "
        "{%0,%1,%2,%3}, {%4,%5,%6,%7}, {%8,%9}, {%0,%1,%2,%3};"
        : "+f"(c[0]), "+f"(c[1]), "+f"(c[2]), "+f"(c[3])
        : "r"(a[0]), "r"(a[1]), "r"(a[2]), "r"(a[3]), "r"(b[0]), "r"(b[1]));
}
__device__ __forceinline__ void split_bf16(float v, __nv_bfloat16& hi, __nv_bfloat16& lo) {
    hi = __float2bfloat16_rn(v);
    lo = __float2bfloat16_rn(v - __bfloat162float(hi));
}
// pack two floats' bf16(hi) into one u32 (f0 low), return residuals
__device__ __forceinline__ uint32_t pack_hi(float f0, float f1, float& r0, float& r1) {
    __nv_bfloat162 h = __floats2bfloat162_rn(f0, f1);
    uint32_t u = *reinterpret_cast<uint32_t*>(&h);
    r0 = f0 - __uint_as_float(u << 16);
    r1 = f1 - __uint_as_float(u & 0xffff0000u);
    return u;
}
__device__ __forceinline__ uint32_t pack_bf(float f0, float f1) {
    __nv_bfloat162 h = __floats2bfloat162_rn(f0, f1);
    return *reinterpret_cast<uint32_t*>(&h);
}
__device__ __forceinline__ void sts16(uint32_t addr, uint32_t a, uint32_t b,
                                      uint32_t c, uint32_t d) {
    asm volatile("st.shared.v4.b32 [%0], {%1, %2, %3, %4};"
                 :: "r"(addr), "r"(a), "r"(b), "r"(c), "r"(d) : "memory");
}

// ---------------------------------------------------------------------------
// Kernel 1: NCHW -> NHWC transpose
// ---------------------------------------------------------------------------
__global__ void k_transpose(const float* __restrict__ x) {
    __shared__ float t[32][33];
    int n   = blockIdx.z;
    int hw0 = blockIdx.x * 32;
    int c0  = blockIdx.y * 32;
    int tx = threadIdx.x, ty = threadIdx.y;
    const float* xin = x + (size_t)n * CIN * HWSZ;
    #pragma unroll
    for (int i = 0; i < 4; i++) {
        int c = c0 + ty + i * 8;
        t[ty + i * 8][tx] = xin[(size_t)c * HWSZ + hw0 + tx];
    }
    __syncthreads();
    float* xo = g_xnhwc + (size_t)n * HWSZ * CIN;
    #pragma unroll
    for (int i = 0; i < 4; i++) {
        int hw = hw0 + ty + i * 8;
        xo[(size_t)hw * CIN + c0 + tx] = t[tx][ty + i * 8];
    }
}

// ---------------------------------------------------------------------------
// Kernel 2: weight -> B[co][ker*256+ci], split bf16 hi/lo
// ---------------------------------------------------------------------------
__global__ void k_wt(const float* __restrict__ w) {
    int idx = blockIdx.x * 256 + threadIdx.x;   // COUT*KD
    int kk = idx % KD;
    int co = idx / KD;
    int ker = kk >> 8;
    int ci  = kk & 255;
    float v = w[((size_t)co * CIN + ci) * KKER + ker];
    __nv_bfloat16 hi, lo;
    split_bf16(v, hi, lo);
    g_Bhi[idx] = hi;
    g_Blo[idx] = lo;
}

// ---------------------------------------------------------------------------
// Fused kernel: implicit GEMM. C[m,co] = sum_k gather(m,k) * B[co,k] + bias
// BM=64, BN=256, BK=32, 256 threads, 8 warps (2M x 4N), warp tile 32x64.
// A tile produced in-kernel (bilinear gather, split bf16); B via cp.async.
// Double buffered; 2 CTAs/SM.
// ---------------------------------------------------------------------------
#define BK 32
#define NCHUNK (KD / BK)        // 72
#define ROWB 80
#define A_MAT (64 * ROWB)       // 5120
#define B_MAT (256 * ROWB)      // 20480
#define OFF_AHI 0
#define OFF_ALO A_MAT
#define OFF_BHI (2 * A_MAT)
#define OFF_BLO (2 * A_MAT + B_MAT)
#define STAGE_BYTES (2 * A_MAT + 2 * B_MAT)     // 51200
#define SMEM_TOTAL (2 * STAGE_BYTES)            // 102400

__global__ __launch_bounds__(256, 2) void k_fused(const float* __restrict__ offset,
                                                  const float* __restrict__ mask,
                                                  const float* __restrict__ bias,
                                                  float* __restrict__ out) {
    extern __shared__ char smem[];
    uint32_t sbase = smem_u32(smem);
    int tid  = threadIdx.x;
    int lane = tid & 31;
    int wid  = tid >> 5;
    int wm   = wid & 1;          // M warp (2)
    int wn   = wid >> 1;         // N warp (4)
    int m0 = blockIdx.x * 64;

    // this thread's pixel + channel quad
    int p = tid >> 2;            // 0..63 local pixel
    int q = tid & 3;             // channel quad (8 ch)
    int mg = m0 + p;
    int n_img = mg / HWSZ;
    int hw = mg - n_img * HWSZ;
    int ho = hw / WW, wo = hw - ho * WW;
    const float* xb = g_xnhwc + (size_t)n_img * HWSZ * CIN;

    // bilinear coord state (per current ker)
    float cw0, cw1, cw2, cw3;
    int   co0, co1, co2, co3;

    auto load_coords = [&](int ker) {
        float dy = offset[((size_t)n_img * 18 + 2 * ker)     * HWSZ + hw];
        float dx = offset[((size_t)n_img * 18 + 2 * ker + 1) * HWSZ + hw];
        float mm = mask  [((size_t)n_img * KKER + ker)       * HWSZ + hw];
        float py = dy + (float)(ker / 3) + (float)(ho - 1);
        float px = dx + (float)(ker % 3) + (float)(wo - 1);
        float fy = floorf(py), fx = floorf(px);
        int y0 = (int)fy, x0 = (int)fx;
        float wy1 = py - fy, wx1 = px - fx;
        float wy0 = 1.0f - wy1, wx0 = 1.0f - wx1;
        bool yv0 = (y0 >= 0) && (y0 < HH);
        bool yv1 = (y0 + 1 >= 0) && (y0 + 1 < HH);
        bool xv0 = (x0 >= 0) && (x0 < WW);
        bool xv1 = (x0 + 1 >= 0) && (x0 + 1 < WW);
        cw0 = (yv0 && xv0) ? wy0 * wx0 * mm : 0.0f;
        cw1 = (yv0 && xv1) ? wy0 * wx1 * mm : 0.0f;
        cw2 = (yv1 && xv0) ? wy1 * wx0 * mm : 0.0f;
        cw3 = (yv1 && xv1) ? wy1 * wx1 * mm : 0.0f;
        int yc0 = min(max(y0, 0), HH - 1), yc1 = min(max(y0 + 1, 0), HH - 1);
        int xc0 = min(max(x0, 0), WW - 1), xc1 = min(max(x0 + 1, 0), WW - 1);
        co0 = (yc0 * WW + xc0) * CIN;
        co1 = (yc0 * WW + xc1) * CIN;
        co2 = (yc1 * WW + xc0) * CIN;
        co3 = (yc1 * WW + xc1) * CIN;
    };

    float4 gv[8];
    auto issue_gather = [&](int kt) {
        int ci0 = (kt & 7) * 32 + q * 8;
        gv[0] = *reinterpret_cast<const float4*>(xb + co0 + ci0);
        gv[1] = *reinterpret_cast<const float4*>(xb + co0 + ci0 + 4);
        gv[2] = *reinterpret_cast<const float4*>(xb + co1 + ci0);
        gv[3] = *reinterpret_cast<const float4*>(xb + co1 + ci0 + 4);
        gv[4] = *reinterpret_cast<const float4*>(xb + co2 + ci0);
        gv[5] = *reinterpret_cast<const float4*>(xb + co2 + ci0 + 4);
        gv[6] = *reinterpret_cast<const float4*>(xb + co3 + ci0);
        gv[7] = *reinterpret_cast<const float4*>(xb + co3 + ci0 + 4);
    };

    auto sts_A = [&](int buf) {
        uint32_t sb = sbase + buf * STAGE_BYTES;
        float f[8];
        f[0] = cw0 * gv[0].x + cw1 * gv[2].x + cw2 * gv[4].x + cw3 * gv[6].x;
        f[1] = cw0 * gv[0].y + cw1 * gv[2].y + cw2 * gv[4].y + cw3 * gv[6].y;
        f[2] = cw0 * gv[0].z + cw1 * gv[2].z + cw2 * gv[4].z + cw3 * gv[6].z;
        f[3] = cw0 * gv[0].w + cw1 * gv[2].w + cw2 * gv[4].w + cw3 * gv[6].w;
        f[4] = cw0 * gv[1].x + cw1 * gv[3].x + cw2 * gv[5].x + cw3 * gv[7].x;
        f[5] = cw0 * gv[1].y + cw1 * gv[3].y + cw2 * gv[5].y + cw3 * gv[7].y;
        f[6] = cw0 * gv[1].z + cw1 * gv[3].z + cw2 * gv[5].z + cw3 * gv[7].z;
        f[7] = cw0 * gv[1].w + cw1 * gv[3].w + cw2 * gv[5].w + cw3 * gv[7].w;
        float r0, r1, r2, r3, r4, r5, r6, r7;
        uint32_t h0 = pack_hi(f[0], f[1], r0, r1);
        uint32_t h1 = pack_hi(f[2], f[3], r2, r3);
        uint32_t h2 = pack_hi(f[4], f[5], r4, r5);
        uint32_t h3 = pack_hi(f[6], f[7], r6, r7);
        uint32_t l0 = pack_bf(r0, r1);
        uint32_t l1 = pack_bf(r2, r3);
        uint32_t l2 = pack_bf(r4, r5);
        uint32_t l3 = pack_bf(r6, r7);
        sts16(sb + OFF_AHI + p * ROWB + q * 16, h0, h1, h2, h3);
        sts16(sb + OFF_ALO + p * ROWB + q * 16, l0, l1, l2, l3);
    };

    auto issue_B = [&](int kt, int buf) {
        uint32_t sb = sbase + buf * STAGE_BYTES;
        int kel = kt * BK;
        const __nv_bfloat16* bh = g_Bhi + (size_t)tid * KD + kel;
        const __nv_bfloat16* bl = g_Blo + (size_t)tid * KD + kel;
        #pragma unroll
        for (int c = 0; c < 4; c++)
            cp_async16(sb + OFF_BHI + tid * ROWB + c * 16, bh + c * 8);
        #pragma unroll
        for (int c = 0; c < 4; c++)
            cp_async16(sb + OFF_BLO + tid * ROWB + c * 16, bl + c * 8);
    };

    float acc[2][8][4];
    #pragma unroll
    for (int i = 0; i < 2; i++)
        #pragma unroll
        for (int j = 0; j < 8; j++)
            #pragma unroll
            for (int r = 0; r < 4; r++) acc[i][j][r] = 0.0f;

    // ldmatrix lane addressing (validated in R3)
    int a_lrow = (lane & 7) + ((lane >> 3) & 1) * 8;
    int a_lc   = (lane >> 4) & 1;
    int b_lrow = (lane & 7) + ((lane >> 4) & 1) * 8;
    int b_lc   = (lane >> 3) & 1;

    // prologue: stage 0
    load_coords(0);
    issue_gather(0);
    issue_B(0, 0);
    cp_commit();
    sts_A(0);

    for (int kt = 0; kt < NCHUNK; kt++) {
        int buf  = kt & 1;
        int nbuf = buf ^ 1;
        if (kt + 1 < NCHUNK) {
            int kn = kt + 1;
            if ((kn & 7) == 0) load_coords(kn >> 3);
            issue_gather(kn);
            issue_B(kn, nbuf);
        }
        cp_commit();
        cp_wait<1>();
        __syncthreads();
        if (kt + 1 < NCHUNK) sts_A(nbuf);

        uint32_t sb = sbase + buf * STAGE_BYTES;
        #pragma unroll
        for (int ks = 0; ks < 2; ks++) {
            uint32_t Ah[2][4], Al[2][4], Bt[4][4];
            #pragma unroll
            for (int mt = 0; mt < 2; mt++) {
                int row = wm * 32 + mt * 16 + a_lrow;
                int c   = 2 * ks + a_lc;
                ldsm4(Ah[mt], sb + OFF_AHI + row * ROWB + c * 16);
                ldsm4(Al[mt], sb + OFF_ALO + row * ROWB + c * 16);
            }
            // B hi: Ah*Bh + Al*Bh
            #pragma unroll
            for (int pg = 0; pg < 4; pg++) {
                int row = wn * 64 + pg * 16 + b_lrow;
                int c   = 2 * ks + b_lc;
                ldsm4(Bt[pg], sb + OFF_BHI + row * ROWB + c * 16);
            }
            #pragma unroll
            for (int mt = 0; mt < 2; mt++)
                #pragma unroll
                for (int nt = 0; nt < 8; nt++) {
                    const uint32_t* b = &Bt[nt >> 1][(nt & 1) * 2];
                    mma_bf16(acc[mt][nt], Ah[mt], b);
                    mma_bf16(acc[mt][nt], Al[mt], b);
                }
            // B lo: Ah*Bl
            #pragma unroll
            for (int pg = 0; pg < 4; pg++) {
                int row = wn * 64 + pg * 16 + b_lrow;
                int c   = 2 * ks + b_lc;
                ldsm4(Bt[pg], sb + OFF_BLO + row * ROWB + c * 16);
            }
            #pragma unroll
            for (int mt = 0; mt < 2; mt++)
                #pragma unroll
                for (int nt = 0; nt < 8; nt++) {
                    const uint32_t* b = &Bt[nt >> 1][(nt & 1) * 2];
                    mma_bf16(acc[mt][nt], Ah[mt], b);
                }
        }
        __syncthreads();
    }

    // epilogue: transpose through smem -> coalesced NCHW float4 writes
    float* ep = reinterpret_cast<float*>(smem);   // [256 co][68 m]
    #pragma unroll
    for (int mt = 0; mt < 2; mt++)
        #pragma unroll
        for (int nt = 0; nt < 8; nt++)
            #pragma unroll
            for (int r = 0; r < 4; r++) {
                int m_l  = wm * 32 + mt * 16 + (lane >> 2) + ((r >> 1) ? 8 : 0);
                int co_l = wn * 64 + nt * 8 + (lane & 3) * 2 + (r & 1);
                ep[co_l * 68 + m_l] = acc[mt][nt][r];
            }
    __syncthreads();
    int img  = m0 / HWSZ;
    int hw0c = m0 - img * HWSZ;
    #pragma unroll
    for (int it = 0; it < 16; it++) {
        int idx = tid + it * 256;     // 0..4095
        int co  = idx >> 4;
        int mq  = (idx & 15) * 4;
        float4 v = *reinterpret_cast<float4*>(&ep[co * 68 + mq]);
        float bv = bias[co];
        v.x += bv; v.y += bv; v.z += bv; v.w += bv;
        float* op = out + ((size_t)img * COUT + co) * HWSZ + hw0c + mq;
        *reinterpret_cast<float4*>(op) = v;
    }
}

// ---------------------------------------------------------------------------
// Launch
// ---------------------------------------------------------------------------
extern "C" void kernel_launch(void* const* d_in, const int* in_sizes, int n_in,
                              void* d_out, int out_size) {
    const float* x      = (const float*)d_in[0];
    const float* offset = (const float*)d_in[1];
    const float* mask   = (const float*)d_in[2];
    const float* weight = (const float*)d_in[3];
    const float* bias   = (const float*)d_in[4];
    float* out = (float*)d_out;

    {
        dim3 grid(HWSZ / 32, CIN / 32, NN);
        dim3 block(32, 8);
        k_transpose<<<grid, block>>>(x);
    }
    k_wt<<<KD, 256>>>(weight);
    {
        static bool attr_set = false;
        if (!attr_set) {
            cudaFuncSetAttribute(k_fused,
                                 cudaFuncAttributeMaxDynamicSharedMemorySize,
                                 SMEM_TOTAL);
            attr_set = true;
        }
        k_fused<<<M_TOTAL / 64, 256, SMEM_TOTAL>>>(offset, mask, bias, out);
    }
}

// round 6
// speedup vs baseline: 1.9374x; 1.9374x over previous
#include <cuda_runtime.h>
#include <cuda_fp16.h>
#include <cstdint>

#define CIN 256
#define COUT 256
#define HH 56
#define WW 56
#define NN 8
#define KKER 9
#define HWSZ (HH*WW)            // 3136
#define M_TOTAL (NN*HWSZ)       // 25088
#define KD (KKER*CIN)           // 2304

// Scratch (device globals — no runtime allocation allowed)
__device__ float  g_xnhwc[(size_t)NN*HWSZ*CIN];     // 25.7 MB fp32
__device__ __half g_Vh[(size_t)M_TOTAL*KD];         // 115.6 MB fp16
__device__ __half g_Bh[(size_t)COUT*KD];            // 1.18 MB fp16

// ---------------------------------------------------------------------------
// helpers
// ---------------------------------------------------------------------------
__device__ __forceinline__ uint32_t smem_u32(const void* p) {
    uint32_t a;
    asm("{ .reg .u64 t; cvta.to.shared.u64 t, %1; cvt.u32.u64 %0, t; }"
        : "=r"(a) : "l"(p));
    return a;
}
__device__ __forceinline__ void cp_async16(uint32_t saddr, const void* gptr) {
    asm volatile("cp.async.cg.shared.global [%0], [%1], 16;"
                 :: "r"(saddr), "l"(__cvta_generic_to_global(gptr)) : "memory");
}
__device__ __forceinline__ void cp_commit() {
    asm volatile("cp.async.commit_group;" ::: "memory");
}
template <int N>
__device__ __forceinline__ void cp_wait() {
    asm volatile("cp.async.wait_group %0;" :: "n"(N) : "memory");
}
__device__ __forceinline__ void ldsm4(uint32_t* d, uint32_t addr) {
    asm volatile("ldmatrix.sync.aligned.m8n8.x4.shared.b16 {%0,%1,%2,%3}, [%4];"
                 : "=r"(d[0]), "=r"(d[1]), "=r"(d[2]), "=r"(d[3]) : "r"(addr));
}
__device__ __forceinline__ void mma_f16(float* c, const uint32_t* a, const uint32_t* b) {
    asm volatile(
        "mma.sync.aligned.m16n8k16.row.col.f32.f16.f16.f32 "
        "{%0,%1,%2,%3}, {%4,%5,%6,%7}, {%8,%9}, {%0,%1,%2,%3};"
        : "+f"(c[0]), "+f"(c[1]), "+f"(c[2]), "+f"(c[3])
        : "r"(a[0]), "r"(a[1]), "r"(a[2]), "r"(a[3]), "r"(b[0]), "r"(b[1]));
}

// ---------------------------------------------------------------------------
// Kernel 1: NCHW -> NHWC transpose (fp32)
// ---------------------------------------------------------------------------
__global__ void k_transpose(const float* __restrict__ x) {
    __shared__ float t[32][33];
    int n   = blockIdx.z;
    int hw0 = blockIdx.x * 32;
    int c0  = blockIdx.y * 32;
    int tx = threadIdx.x, ty = threadIdx.y;
    const float* xin = x + (size_t)n * CIN * HWSZ;
    #pragma unroll
    for (int i = 0; i < 4; i++) {
        int c = c0 + ty + i * 8;
        t[ty + i * 8][tx] = xin[(size_t)c * HWSZ + hw0 + tx];
    }
    __syncthreads();
    float* xo = g_xnhwc + (size_t)n * HWSZ * CIN;
    #pragma unroll
    for (int i = 0; i < 4; i++) {
        int hw = hw0 + ty + i * 8;
        xo[(size_t)hw * CIN + c0 + tx] = t[tx][ty + i * 8];
    }
}

// ---------------------------------------------------------------------------
// Kernel 2: weight -> Bh[co][ker*256+ci] fp16
// ---------------------------------------------------------------------------
__global__ void k_wt(const float* __restrict__ w) {
    int idx = blockIdx.x * 256 + threadIdx.x;   // COUT*KD
    int kk = idx % KD;
    int co = idx / KD;
    int ker = kk >> 8;
    int ci  = kk & 255;
    g_Bh[idx] = __float2half_rn(w[((size_t)co * CIN + ci) * KKER + ker]);
}

// ---------------------------------------------------------------------------
// Kernel 3: bilinear gather + modulation -> Vh[m][ker*256+c] fp16
// ---------------------------------------------------------------------------
__global__ __launch_bounds__(256) void k_gather(const float* __restrict__ offset,
                                                const float* __restrict__ mask) {
    int pix = blockIdx.x;
    int c   = threadIdx.x;
    int n   = pix / HWSZ;
    int hw  = pix % HWSZ;
    int ho  = hw / WW, wo = hw % WW;
    const float* xb = g_xnhwc + (size_t)n * HWSZ * CIN;
    size_t vbase = (size_t)pix * KD;

    #pragma unroll
    for (int k = 0; k < KKER; k++) {
        float dy = offset[((size_t)n * 18 + 2 * k)     * HWSZ + hw];
        float dx = offset[((size_t)n * 18 + 2 * k + 1) * HWSZ + hw];
        float mm = mask  [((size_t)n * KKER + k)       * HWSZ + hw];
        float py = dy + (float)(k / 3) + (float)(ho - 1);
        float px = dx + (float)(k % 3) + (float)(wo - 1);
        float fy = floorf(py), fx = floorf(px);
        int y0 = (int)fy, x0 = (int)fx;
        float wy1 = py - fy, wx1 = px - fx;
        float wy0 = 1.0f - wy1, wx0 = 1.0f - wx1;

        float acc = 0.0f;
        if (y0 >= 0 && y0 < HH && x0 >= 0 && x0 < WW)
            acc += (wy0 * wx0) * xb[(size_t)(y0 * WW + x0) * CIN + c];
        if (y0 >= 0 && y0 < HH && x0 + 1 < WW && x0 + 1 >= 0)
            acc += (wy0 * wx1) * xb[(size_t)(y0 * WW + x0 + 1) * CIN + c];
        if (y0 + 1 >= 0 && y0 + 1 < HH && x0 >= 0 && x0 < WW)
            acc += (wy1 * wx0) * xb[(size_t)((y0 + 1) * WW + x0) * CIN + c];
        if (y0 + 1 < HH && y0 + 1 >= 0 && x0 + 1 < WW && x0 + 1 >= 0)
            acc += (wy1 * wx1) * xb[(size_t)((y0 + 1) * WW + x0 + 1) * CIN + c];
        g_Vh[vbase + k * CIN + c] = __float2half_rn(acc * mm);
    }
}

// ---------------------------------------------------------------------------
// Kernel 4: fp16 single-pass HMMA GEMM  C[25088,256] = Vh * Bh^T  (+bias)
// BM=64, BN=256 (full N -> A read once), BK=32, 256 thr, 8 warps (2M x 4N),
// warp tile 32x64, 4-stage cp.async pipeline, 2 CTAs/SM.
// ---------------------------------------------------------------------------
#define BK 32
#define NCHUNK (KD / BK)        // 72
#define ROWB 80                 // 32 fp16 = 64B data + 16B pad
#define A_MAT (64 * ROWB)       // 5120
#define B_MAT (256 * ROWB)      // 20480
#define OFF_A 0
#define OFF_B A_MAT
#define STAGE_BYTES (A_MAT + B_MAT)             // 25600
#define NSTAGE 4
#define SMEM_TOTAL (NSTAGE * STAGE_BYTES)       // 102400

__global__ __launch_bounds__(256, 2) void k_gemm(const float* __restrict__ bias,
                                                 float* __restrict__ out) {
    extern __shared__ char smem[];
    uint32_t sbase = smem_u32(smem);
    int tid  = threadIdx.x;
    int lane = tid & 31;
    int wid  = tid >> 5;
    int wm   = wid & 1;          // M warp (2)
    int wn   = wid >> 1;         // N warp (4)
    int m0 = blockIdx.x * 64;

    const __half* Ag = g_Vh + (size_t)m0 * KD;
    const __half* Bg = g_Bh;

    // cp.async coords: A 64 rows x 4 segs = 256 -> 1/thread; B 256 rows x 4 = 1024 -> 4/thread
    int a_row = tid >> 2;
    int a_seg = tid & 3;
    int b_row0 = tid >> 2;       // +64,+128,+192
    int b_seg  = tid & 3;

    auto issue = [&](int kt) {
        uint32_t sb = sbase + (kt % NSTAGE) * STAGE_BYTES;
        int kel = kt * BK;
        cp_async16(sb + OFF_A + a_row * ROWB + a_seg * 16,
                   Ag + (size_t)a_row * KD + kel + a_seg * 8);
        #pragma unroll
        for (int r = 0; r < 4; r++) {
            int row = b_row0 + r * 64;
            cp_async16(sb + OFF_B + row * ROWB + b_seg * 16,
                       Bg + (size_t)row * KD + kel + b_seg * 8);
        }
    };

    float acc[2][8][4];
    #pragma unroll
    for (int i = 0; i < 2; i++)
        #pragma unroll
        for (int j = 0; j < 8; j++)
            #pragma unroll
            for (int r = 0; r < 4; r++) acc[i][j][r] = 0.0f;

    // ldmatrix lane addressing (validated R3/R4)
    int a_lrow = (lane & 7) + ((lane >> 3) & 1) * 8;
    int a_lc   = (lane >> 4) & 1;
    int b_lrow = (lane & 7) + ((lane >> 4) & 1) * 8;
    int b_lc   = (lane >> 3) & 1;

    issue(0); cp_commit();
    issue(1); cp_commit();
    issue(2); cp_commit();

    for (int kt = 0; kt < NCHUNK; kt++) {
        cp_wait<2>();
        __syncthreads();
        if (kt + 3 < NCHUNK) issue(kt + 3);
        cp_commit();

        uint32_t sb = sbase + (kt % NSTAGE) * STAGE_BYTES;
        #pragma unroll
        for (int ks = 0; ks < 2; ks++) {
            uint32_t Ah[2][4], Bt[4][4];
            #pragma unroll
            for (int mt = 0; mt < 2; mt++) {
                int row = wm * 32 + mt * 16 + a_lrow;
                int c   = 2 * ks + a_lc;
                ldsm4(Ah[mt], sb + OFF_A + row * ROWB + c * 16);
            }
            #pragma unroll
            for (int pg = 0; pg < 4; pg++) {
                int row = wn * 64 + pg * 16 + b_lrow;
                int c   = 2 * ks + b_lc;
                ldsm4(Bt[pg], sb + OFF_B + row * ROWB + c * 16);
            }
            #pragma unroll
            for (int mt = 0; mt < 2; mt++)
                #pragma unroll
                for (int nt = 0; nt < 8; nt++) {
                    const uint32_t* b = &Bt[nt >> 1][(nt & 1) * 2];
                    mma_f16(acc[mt][nt], Ah[mt], b);
                }
        }
    }

    // epilogue: transpose through smem -> coalesced NCHW float4 writes (R4-validated)
    __syncthreads();
    float* ep = reinterpret_cast<float*>(smem);   // [256 co][68 m]
    #pragma unroll
    for (int mt = 0; mt < 2; mt++)
        #pragma unroll
        for (int nt = 0; nt < 8; nt++)
            #pragma unroll
            for (int r = 0; r < 4; r++) {
                int m_l  = wm * 32 + mt * 16 + (lane >> 2) + ((r >> 1) ? 8 : 0);
                int co_l = wn * 64 + nt * 8 + (lane & 3) * 2 + (r & 1);
                ep[co_l * 68 + m_l] = acc[mt][nt][r];
            }
    __syncthreads();
    int img  = m0 / HWSZ;
    int hw0c = m0 - img * HWSZ;
    #pragma unroll
    for (int it = 0; it < 16; it++) {
        int idx = tid + it * 256;     // 0..4095
        int co  = idx >> 4;
        int mq  = (idx & 15) * 4;
        float4 v = *reinterpret_cast<float4*>(&ep[co * 68 + mq]);
        float bv = bias[co];
        v.x += bv; v.y += bv; v.z += bv; v.w += bv;
        float* op = out + ((size_t)img * COUT + co) * HWSZ + hw0c + mq;
        *reinterpret_cast<float4*>(op) = v;
    }
}

// ---------------------------------------------------------------------------
// Launch
// ---------------------------------------------------------------------------
extern "C" void kernel_launch(void* const* d_in, const int* in_sizes, int n_in,
                              void* d_out, int out_size) {
    const float* x      = (const float*)d_in[0];
    const float* offset = (const float*)d_in[1];
    const float* mask   = (const float*)d_in[2];
    const float* weight = (const float*)d_in[3];
    const float* bias   = (const float*)d_in[4];
    float* out = (float*)d_out;

    {
        dim3 grid(HWSZ / 32, CIN / 32, NN);
        dim3 block(32, 8);
        k_transpose<<<grid, block>>>(x);
    }
    k_wt<<<KD, 256>>>(weight);
    k_gather<<<M_TOTAL, 256>>>(offset, mask);
    {
        static bool attr_set = false;
        if (!attr_set) {
            cudaFuncSetAttribute(k_gemm,
                                 cudaFuncAttributeMaxDynamicSharedMemorySize,
                                 SMEM_TOTAL);
            attr_set = true;
        }
        k_gemm<<<M_TOTAL / 64, 256, SMEM_TOTAL>>>(bias, out);
    }
}